// round 14
// baseline (speedup 1.0000x reference)
#include <cuda_runtime.h>
#include <math.h>

#define BB  64
#define LCC 512
#define LQQ 64
#define DD  256

// ---------------------------------------------------------------------------
// tf32 mma (m16n8k8, row.col, fp32 accum) — operands are RAW fp32 bits
// ---------------------------------------------------------------------------
__device__ __forceinline__ void mma8(float& d0, float& d1, float& d2, float& d3,
                                     unsigned a0, unsigned a1, unsigned a2, unsigned a3,
                                     unsigned b0, unsigned b1) {
    asm("mma.sync.aligned.m16n8k8.row.col.f32.tf32.tf32.f32 "
        "{%0,%1,%2,%3},{%4,%5,%6,%7},{%8,%9},{%0,%1,%2,%3};"
        : "+f"(d0), "+f"(d1), "+f"(d2), "+f"(d3)
        : "r"(a0), "r"(a1), "r"(a2), "r"(a3), "r"(b0), "r"(b1));
}
__device__ __forceinline__ unsigned sm2u(const void* p) {
    unsigned r;
    asm("{.reg .u64 t; cvta.to.shared.u64 t, %1; cvt.u32.u64 %0, t;}" : "=r"(r) : "l"(p));
    return r;
}
__device__ __forceinline__ void stg_cs(float* p, float4 v) {
    asm volatile("st.global.cs.v4.f32 [%0], {%1,%2,%3,%4};"
                 :: "l"(p), "f"(v.x), "f"(v.y), "f"(v.z), "f"(v.w));
}
#define CPA16(dst, src) asm volatile("cp.async.ca.shared.global [%0], [%1], 16;" :: "r"(dst), "l"(src))
#define CPCOMMIT()      asm volatile("cp.async.commit_group;")
#define CPWAIT1()       asm volatile("cp.async.wait_group 1;")
#define CPWAIT0()       asm volatile("cp.async.wait_group 0;")

// Scratch (device globals; no allocation allowed)
__device__ float g_Qp[(size_t)BB * LQQ * DD];            // wi*q + wc
__device__ float g_t[BB * LQQ];                          // <q,wq> + bias
__device__ float g_S1[(size_t)BB * LCC * LQQ];           // row-softmax(S)
__device__ float g_rs[BB * LCC];                         // unshifted row expsums
__device__ float g_cpart[4 * BB * LQQ];                  // per-i-block col expsum partials
__device__ float g_C2[(size_t)BB * LQQ * DD];            // S2^T @ contex

// ---------------------------------------------------------------------------
// K0: Q'[b,j,d] = wi[d]*q[b,j,d] + wc[d];  t[b,j] = <q[b,j], wq> + bias
// ---------------------------------------------------------------------------
__global__ void k0_prep(const float* __restrict__ q,
                        const float* __restrict__ W,
                        const float* __restrict__ bias) {
    const int bj = blockIdx.x;
    const int d  = threadIdx.x;
    const float qv = q[(size_t)bj * DD + d];
    g_Qp[(size_t)bj * DD + d] = fmaf(W[2 * DD + d], qv, W[DD + d]);

    float v = qv * W[d];
    #pragma unroll
    for (int o = 16; o > 0; o >>= 1) v += __shfl_xor_sync(0xffffffffu, v, o);
    __shared__ float red[8];
    if ((threadIdx.x & 31) == 0) red[threadIdx.x >> 5] = v;
    __syncthreads();
    if (threadIdx.x == 0) {
        float s = 0.f;
        #pragma unroll
        for (int i = 0; i < 8; i++) s += red[i];
        g_t[bj] = s + bias[0];
    }
}

// ---------------------------------------------------------------------------
// K1: S = contex @ Q'^T + t via raw-fp32 tf32 mma, 3-stage cp.async pipeline.
// Block 128(i) x 64(j), 256 thr = 8 warps (16x64), K=256. grid=(4, B)
// Outputs: S1 (row softmax), rs (row expsums), col expsum partials.
// ---------------------------------------------------------------------------
__global__ void __launch_bounds__(256, 2) k1_score(const float* __restrict__ contex) {
    const int b  = blockIdx.y;
    const int i0 = blockIdx.x * 128;
    const int tid = threadIdx.x;
    const int warp = tid >> 5, lane = tid & 31;
    const int g = lane >> 2, t = lane & 3;
    const int wm = warp * 16;

    extern __shared__ float sm[];
    float* As   = sm;                 // 3 x 128 x 36 = 13824
    float* Bs   = sm + 13824;         // 3 x 64 x 36  = 6912
    float* ts   = sm + 20736;         // 64
    float* scol = sm + 20800;         // 8 x 64 = 512
    if (tid < 64) ts[tid] = g_t[b * LQQ + tid];

    const float* Cb = contex + (size_t)b * LCC * DD;
    const float* Qp = g_Qp  + (size_t)b * LQQ * DD;

    const int alr = tid >> 1, ako = (tid & 1) * 16;   // A: 4x16B per stage
    const int bjr = tid >> 2, bko = (tid & 3) * 8;    // B: 2x16B per stage
    const unsigned smu = sm2u(sm);

    auto cpStage = [&](int s) {
        const int buf = s % 3;
        const float* ga = &Cb[(size_t)(i0 + alr) * DD + s * 32 + ako];
        unsigned da = smu + (unsigned)((buf * 128 + alr) * 36 + ako) * 4u;
        CPA16(da,      ga);     CPA16(da + 16, ga + 4);
        CPA16(da + 32, ga + 8); CPA16(da + 48, ga + 12);
        const float* gb = &Qp[(size_t)bjr * DD + s * 32 + bko];
        unsigned db = smu + (unsigned)(13824 + (buf * 64 + bjr) * 36 + bko) * 4u;
        CPA16(db, gb); CPA16(db + 16, gb + 4);
        CPCOMMIT();
    };

    float acc[8][4];
    #pragma unroll
    for (int nt = 0; nt < 8; nt++)
        #pragma unroll
        for (int r = 0; r < 4; r++) acc[nt][r] = 0.f;

    cpStage(0); cpStage(1);

    #pragma unroll
    for (int it = 0; it < 8; it++) {
        if (it < 7) { CPWAIT1(); } else { CPWAIT0(); }
        __syncthreads();
        if (it + 2 < 8) cpStage(it + 2);
        const float* Ab = As + (size_t)(it % 3) * 128 * 36;
        const float* Bb = Bs + (size_t)(it % 3) * 64 * 36;
        #pragma unroll
        for (int kc = 0; kc < 32; kc += 8) {
            unsigned a0 = *(const unsigned*)&Ab[(size_t)(wm + g) * 36 + kc + t];
            unsigned a1 = *(const unsigned*)&Ab[(size_t)(wm + 8 + g) * 36 + kc + t];
            unsigned a2 = *(const unsigned*)&Ab[(size_t)(wm + g) * 36 + kc + t + 4];
            unsigned a3 = *(const unsigned*)&Ab[(size_t)(wm + 8 + g) * 36 + kc + t + 4];
            #pragma unroll
            for (int nt = 0; nt < 8; nt++) {
                unsigned b0 = *(const unsigned*)&Bb[(size_t)(nt * 8 + g) * 36 + kc + t];
                unsigned b1 = *(const unsigned*)&Bb[(size_t)(nt * 8 + g) * 36 + kc + t + 4];
                mma8(acc[nt][0], acc[nt][1], acc[nt][2], acc[nt][3],
                     a0, a1, a2, a3, b0, b1);
            }
        }
        __syncthreads();
    }

    // ---- epilogue: +t[j], col expsums, row softmax -> S1, row sums -> rs ----
    float* S1b = g_S1 + (size_t)b * LCC * LQQ;
    float cs[16];
    #pragma unroll
    for (int c = 0; c < 16; c++) cs[c] = 0.f;

    #pragma unroll
    for (int h = 0; h < 2; h++) {
        const int i = i0 + wm + h * 8 + g;
        float s[16];
        #pragma unroll
        for (int nt = 0; nt < 8; nt++) {
            s[2 * nt]     = acc[nt][2 * h]     + ts[nt * 8 + 2 * t];
            s[2 * nt + 1] = acc[nt][2 * h + 1] + ts[nt * 8 + 2 * t + 1];
        }
        #pragma unroll
        for (int c = 0; c < 16; c++) cs[c] += __expf(s[c]);
        float m = s[0];
        #pragma unroll
        for (int c = 1; c < 16; c++) m = fmaxf(m, s[c]);
        m = fmaxf(m, __shfl_xor_sync(0xffffffffu, m, 1));
        m = fmaxf(m, __shfl_xor_sync(0xffffffffu, m, 2));
        float e[16], sum = 0.f;
        #pragma unroll
        for (int c = 0; c < 16; c++) { e[c] = __expf(s[c] - m); sum += e[c]; }
        sum += __shfl_xor_sync(0xffffffffu, sum, 1);
        sum += __shfl_xor_sync(0xffffffffu, sum, 2);
        const float inv = 1.f / sum;
        #pragma unroll
        for (int nt = 0; nt < 8; nt++) {
            float2 o = make_float2(e[2 * nt] * inv, e[2 * nt + 1] * inv);
            *(float2*)&S1b[(size_t)i * LQQ + nt * 8 + 2 * t] = o;
        }
        if (t == 0) g_rs[b * LCC + i] = sum * __expf(m);
    }
    #pragma unroll
    for (int c = 0; c < 16; c++) {
        cs[c] += __shfl_xor_sync(0xffffffffu, cs[c], 4);
        cs[c] += __shfl_xor_sync(0xffffffffu, cs[c], 8);
        cs[c] += __shfl_xor_sync(0xffffffffu, cs[c], 16);
    }
    if (g == 0) {
        #pragma unroll
        for (int c = 0; c < 16; c++) {
            const int j = (c >> 1) * 8 + 2 * t + (c & 1);
            scol[warp * 64 + j] = cs[c];
        }
    }
    __syncthreads();
    if (tid < 64) {
        float p = 0.f;
        #pragma unroll
        for (int w = 0; w < 8; w++) p += scol[w * 64 + tid];
        g_cpart[blockIdx.x * (BB * LQQ) + b * LQQ + tid] = p;
    }
}

// ---------------------------------------------------------------------------
// K3: C2 = S2^T @ contex, full K=512.  S2[i,j] = S1[i,j]*rs_i*inv_j built on
// the A-fill from L2-hot S1 (no exp).  inv combine folded into prologue.
// Block 64(j) x 64(n), 512 thr = 16 warps 4(m)x4(n), warp tile 16x16.
// A stored [k][j] so the transpose-fill is one float4 STS. grid=(4, B)
// ---------------------------------------------------------------------------
__global__ void __launch_bounds__(512, 2) k3_c2(const float* __restrict__ contex) {
    const int b   = blockIdx.y;
    const int n0  = blockIdx.x * 64;
    const int tid = threadIdx.x;
    const int warp = tid >> 5, lane = tid & 31;
    const int g = lane >> 2, t = lane & 3;
    const int wm = (warp & 3) * 16;
    const int wn = (warp >> 2) * 16;

    extern __shared__ float sm3[];
    float* As   = sm3;                     // 2 x 32 x 68 [k=i][j]
    float* Bs   = sm3 + 4352;              // 3 x 32 x 72 [k][n]
    float* rssm = sm3 + 4352 + 6912;       // 512
    float* sinv = rssm + 512;              // 64

    const float* S1b = g_S1 + (size_t)b * LCC * LQQ;
    const float* Cb  = contex + (size_t)b * LCC * DD;

    rssm[tid] = g_rs[b * LCC + tid];
    if (tid < 64) {
        const int idx = b * LQQ + tid;
        float s = g_cpart[idx] + g_cpart[BB * LQQ + idx]
                + g_cpart[2 * BB * LQQ + idx] + g_cpart[3 * BB * LQQ + idx];
        sinv[tid] = 1.f / s;
    }
    __syncthreads();

    const int iloc = tid >> 4, jo = (tid & 15) * 4;   // A fill: 32 rows x 64 j
    const float4 inv4 = *(const float4*)&sinv[jo];
    const unsigned smu = sm2u(sm3);

    auto cpB = [&](int s) {
        const int buf = s % 3;
        const float* c = &Cb[(size_t)(s * 32 + iloc) * DD + n0 + jo];
        unsigned db = smu + (unsigned)(4352 + (buf * 32 + iloc) * 72 + jo) * 4u;
        CPA16(db, c);
        CPCOMMIT();
    };

    float4 ra; float rsv;
    auto ldA = [&](int s) {
        ra  = *(const float4*)&S1b[(size_t)(s * 32 + iloc) * LQQ + jo];
        rsv = rssm[s * 32 + iloc];
    };
    auto stA = [&](int s) {
        float4 v = make_float4(ra.x * rsv * inv4.x, ra.y * rsv * inv4.y,
                               ra.z * rsv * inv4.z, ra.w * rsv * inv4.w);
        *(float4*)&As[(size_t)((s & 1) * 32 + iloc) * 68 + jo] = v;
    };

    float acc[2][4];
    #pragma unroll
    for (int nt = 0; nt < 2; nt++)
        #pragma unroll
        for (int r = 0; r < 4; r++) acc[nt][r] = 0.f;

    cpB(0); cpB(1);
    ldA(0); stA(0);

    #pragma unroll 4
    for (int it = 0; it < 16; it++) {
        if (it < 15) { CPWAIT1(); } else { CPWAIT0(); }
        __syncthreads();
        if (it + 2 < 16) cpB(it + 2);
        if (it < 15) ldA(it + 1);

        const float* Ab = As + (size_t)(it & 1) * 32 * 68;
        const float* Bb = Bs + (size_t)(it % 3) * 32 * 72;
        #pragma unroll
        for (int kc = 0; kc < 32; kc += 8) {
            unsigned a0 = *(const unsigned*)&Ab[(size_t)(kc + t) * 68 + wm + g];
            unsigned a1 = *(const unsigned*)&Ab[(size_t)(kc + t) * 68 + wm + 8 + g];
            unsigned a2 = *(const unsigned*)&Ab[(size_t)(kc + t + 4) * 68 + wm + g];
            unsigned a3 = *(const unsigned*)&Ab[(size_t)(kc + t + 4) * 68 + wm + 8 + g];
            #pragma unroll
            for (int nt = 0; nt < 2; nt++) {
                const int n = wn + nt * 8 + g;
                unsigned b0 = *(const unsigned*)&Bb[(size_t)(kc + t) * 72 + n];
                unsigned b1 = *(const unsigned*)&Bb[(size_t)(kc + t + 4) * 72 + n];
                mma8(acc[nt][0], acc[nt][1], acc[nt][2], acc[nt][3],
                     a0, a1, a2, a3, b0, b1);
            }
        }
        if (it < 15) stA(it + 1);
        __syncthreads();
    }

    float* outp = g_C2 + (size_t)b * LQQ * DD;
    #pragma unroll
    for (int h = 0; h < 2; h++) {
        const int j = wm + h * 8 + g;
        #pragma unroll
        for (int nt = 0; nt < 2; nt++) {
            float2 o = make_float2(acc[nt][2 * h], acc[nt][2 * h + 1]);
            *(float2*)&outp[(size_t)j * DD + n0 + wn + nt * 8 + 2 * t] = o;
        }
    }
}

// ---------------------------------------------------------------------------
// K4: one (i-block, chunk) per CTA (R12 structure — max block parallelism).
// One cp.async group loads A tile + both B tiles + CONTEX tile (prefetched,
// so the epilogue has no exposed LDG). A = S1 @ question, Bm = S1 @ C2;
// fused output [contex | A | contex*A | contex*Bm], smem-staged, st.global.cs.
// 3 blocks/SM. grid=(8, B, 4)
// ---------------------------------------------------------------------------
__global__ void __launch_bounds__(256, 3) k4_out(const float* __restrict__ contex,
                                                 const float* __restrict__ question,
                                                 float* __restrict__ out) {
    const int b   = blockIdx.y;
    const int i0  = blockIdx.x * 64;
    const int c0  = blockIdx.z * 64;
    const int tid = threadIdx.x;
    const int warp = tid >> 5, lane = tid & 31;
    const int g = lane >> 2, t = lane & 3;
    const int wm = (warp & 3) * 16;
    const int wn = (warp >> 2) * 32;

    extern __shared__ float sm4[];
    float* As = sm4;                        // 64 x 68 [i][j]
    float* Bq = sm4 + 4352;                 // 64 x 72 [j][n]  (question chunk)
    float* Bc = Bq + 4608;                  // 64 x 72 [j][n]  (C2 chunk)
    float* Cx = Bc + 4608;                  // 64 x 68 [i][n]  (contex tile)

    const float* S1b = g_S1 + (size_t)b * LCC * LQQ;
    const float* Cb  = contex   + (size_t)b * LCC * DD;
    const float* Qb  = question + (size_t)b * LQQ * DD;
    const float* P   = g_C2     + (size_t)b * LQQ * DD;
    float* outb = out + (size_t)b * LCC * 1024;

    const unsigned smu = sm2u(sm4);
    {   // one cp.async group: A tile + both B tiles + contex tile
        const int lr = tid >> 2, o16 = (tid & 3) * 16;
        const float* sa = &S1b[(size_t)(i0 + lr) * LQQ + o16];
        unsigned da = smu + (unsigned)(lr * 68 + o16) * 4u;
        CPA16(da, sa); CPA16(da + 16, sa + 4); CPA16(da + 32, sa + 8); CPA16(da + 48, sa + 12);
        const float* q = &Qb[(size_t)lr * DD + c0 + o16];
        unsigned dq = smu + (unsigned)(4352 + lr * 72 + o16) * 4u;
        CPA16(dq, q); CPA16(dq + 16, q + 4); CPA16(dq + 32, q + 8); CPA16(dq + 48, q + 12);
        const float* p = &P[(size_t)lr * DD + c0 + o16];
        unsigned dc = smu + (unsigned)(4352 + 4608 + lr * 72 + o16) * 4u;
        CPA16(dc, p); CPA16(dc + 16, p + 4); CPA16(dc + 32, p + 8); CPA16(dc + 48, p + 12);
        const float* cx = &Cb[(size_t)(i0 + lr) * DD + c0 + o16];
        unsigned dx = smu + (unsigned)(4352 + 9216 + lr * 68 + o16) * 4u;
        CPA16(dx, cx); CPA16(dx + 16, cx + 4); CPA16(dx + 32, cx + 8); CPA16(dx + 48, cx + 12);
        CPCOMMIT();
    }
    CPWAIT0();
    __syncthreads();

    float accq[4][4], accc[4][4];
    #pragma unroll
    for (int nt = 0; nt < 4; nt++)
        #pragma unroll
        for (int r = 0; r < 4; r++) { accq[nt][r] = 0.f; accc[nt][r] = 0.f; }

    #pragma unroll
    for (int kc = 0; kc < 64; kc += 8) {
        unsigned a0 = *(const unsigned*)&As[(size_t)(wm + g) * 68 + kc + t];
        unsigned a1 = *(const unsigned*)&As[(size_t)(wm + 8 + g) * 68 + kc + t];
        unsigned a2 = *(const unsigned*)&As[(size_t)(wm + g) * 68 + kc + t + 4];
        unsigned a3 = *(const unsigned*)&As[(size_t)(wm + 8 + g) * 68 + kc + t + 4];
        #pragma unroll
        for (int nt = 0; nt < 4; nt++) {
            const int n = wn + nt * 8 + g;
            unsigned q0 = *(const unsigned*)&Bq[(size_t)(kc + t) * 72 + n];
            unsigned q1 = *(const unsigned*)&Bq[(size_t)(kc + t + 4) * 72 + n];
            mma8(accq[nt][0], accq[nt][1], accq[nt][2], accq[nt][3],
                 a0, a1, a2, a3, q0, q1);
            unsigned c0r = *(const unsigned*)&Bc[(size_t)(kc + t) * 72 + n];
            unsigned c1r = *(const unsigned*)&Bc[(size_t)(kc + t + 4) * 72 + n];
            mma8(accc[nt][0], accc[nt][1], accc[nt][2], accc[nt][3],
                 a0, a1, a2, a3, c0r, c1r);
        }
    }
    __syncthreads();   // B tiles consumed -> reuse as fragment stage

    // stage fragments: Bq region holds A-frags, Bc region holds Bm-frags
    #pragma unroll
    for (int h = 0; h < 2; h++) {
        const int r = wm + h * 8 + g;
        #pragma unroll
        for (int nt = 0; nt < 4; nt++) {
            const int c = wn + nt * 8 + 2 * t;
            *(float2*)&Bq[(size_t)r * 72 + c] =
                make_float2(accq[nt][2 * h], accq[nt][2 * h + 1]);
            *(float2*)&Bc[(size_t)r * 72 + c] =
                make_float2(accc[nt][2 * h], accc[nt][2 * h + 1]);
        }
    }
    __syncthreads();

    // coalesced output: 4 passes, all inputs from smem, 4x STG.128.cs per pass
    const int orw = tid >> 4;              // 0..15
    const int occ4 = (tid & 15) * 4;       // 0..60
    #pragma unroll
    for (int p = 0; p < 4; p++) {
        const int r = p * 16 + orw;
        float4 a4 = *(const float4*)&Bq[(size_t)r * 72 + occ4];
        float4 m4 = *(const float4*)&Bc[(size_t)r * 72 + occ4];
        float4 cv = *(const float4*)&Cx[(size_t)r * 68 + occ4];
        float4 pa = make_float4(cv.x * a4.x, cv.y * a4.y, cv.z * a4.z, cv.w * a4.w);
        float4 pb = make_float4(cv.x * m4.x, cv.y * m4.y, cv.z * m4.z, cv.w * m4.w);
        float* orow = &outb[(size_t)(i0 + r) * 1024 + c0 + occ4];
        stg_cs(orow,       cv);   // contex
        stg_cs(orow + 256, a4);   // A
        stg_cs(orow + 512, pa);   // contex * A
        stg_cs(orow + 768, pb);   // contex * Bm
    }
}

// ---------------------------------------------------------------------------
extern "C" void kernel_launch(void* const* d_in, const int* in_sizes, int n_in,
                              void* d_out, int out_size) {
    const float* contex   = (const float*)d_in[0];
    const float* question = (const float*)d_in[1];
    const float* W        = (const float*)d_in[2];
    const float* bias     = (const float*)d_in[3];
    float* out = (float*)d_out;

    const int k1smem = 21312 * (int)sizeof(float);                          // 85248
    const int k3smem = (4352 + 6912 + 512 + 64) * (int)sizeof(float);       // 47360
    const int k4smem = (4352 + 4608 + 4608 + 4352) * (int)sizeof(float);    // 71680
    cudaFuncSetAttribute(k1_score, cudaFuncAttributeMaxDynamicSharedMemorySize, k1smem);
    cudaFuncSetAttribute(k3_c2,    cudaFuncAttributeMaxDynamicSharedMemorySize, k3smem);
    cudaFuncSetAttribute(k4_out,   cudaFuncAttributeMaxDynamicSharedMemorySize, k4smem);

    k0_prep<<<BB * LQQ, 256>>>(question, W, bias);
    k1_score<<<dim3(4, BB), 256, k1smem>>>(contex);
    k3_c2<<<dim3(4, BB), 512, k3smem>>>(contex);
    k4_out<<<dim3(8, BB, 4), 256, k4smem>>>(contex, question, out);
}

// round 15
// speedup vs baseline: 1.0936x; 1.0936x over previous
#include <cuda_runtime.h>
#include <math.h>

#define BB  64
#define LCC 512
#define LQQ 64
#define DD  256

// ---------------------------------------------------------------------------
// tf32 mma (m16n8k8, row.col, fp32 accum) — operands are RAW fp32 bits
// ---------------------------------------------------------------------------
__device__ __forceinline__ void mma8(float& d0, float& d1, float& d2, float& d3,
                                     unsigned a0, unsigned a1, unsigned a2, unsigned a3,
                                     unsigned b0, unsigned b1) {
    asm("mma.sync.aligned.m16n8k8.row.col.f32.tf32.tf32.f32 "
        "{%0,%1,%2,%3},{%4,%5,%6,%7},{%8,%9},{%0,%1,%2,%3};"
        : "+f"(d0), "+f"(d1), "+f"(d2), "+f"(d3)
        : "r"(a0), "r"(a1), "r"(a2), "r"(a3), "r"(b0), "r"(b1));
}
__device__ __forceinline__ unsigned sm2u(const void* p) {
    unsigned r;
    asm("{.reg .u64 t; cvta.to.shared.u64 t, %1; cvt.u32.u64 %0, t;}" : "=r"(r) : "l"(p));
    return r;
}
__device__ __forceinline__ void stg_cs(float* p, float4 v) {
    asm volatile("st.global.cs.v4.f32 [%0], {%1,%2,%3,%4};"
                 :: "l"(p), "f"(v.x), "f"(v.y), "f"(v.z), "f"(v.w));
}
#define CPA16(dst, src) asm volatile("cp.async.ca.shared.global [%0], [%1], 16;" :: "r"(dst), "l"(src))
#define CPCOMMIT()      asm volatile("cp.async.commit_group;")
#define CPWAIT1()       asm volatile("cp.async.wait_group 1;")
#define CPWAIT0()       asm volatile("cp.async.wait_group 0;")

// Scratch (device globals; no allocation allowed)
__device__ float g_t[BB * LQQ];                          // <q,wq> + bias
__device__ float g_S1[(size_t)BB * LCC * LQQ];           // row-softmax(S)
__device__ float g_rs[BB * LCC];                         // unshifted row expsums
__device__ float g_cpart[4 * BB * LQQ];                  // per-i-block col expsum partials
__device__ float g_C2[(size_t)BB * LQQ * DD];            // S2^T @ contex

// ---------------------------------------------------------------------------
// K0: t[b,j] = <q[b,j], wq> + bias  (Q' is now fused into k1's B-fill)
// ---------------------------------------------------------------------------
__global__ void k0_t(const float* __restrict__ q,
                     const float* __restrict__ W,
                     const float* __restrict__ bias) {
    const int bj = blockIdx.x;
    const int d  = threadIdx.x;
    float v = q[(size_t)bj * DD + d] * W[d];
    #pragma unroll
    for (int o = 16; o > 0; o >>= 1) v += __shfl_xor_sync(0xffffffffu, v, o);
    __shared__ float red[8];
    if ((threadIdx.x & 31) == 0) red[threadIdx.x >> 5] = v;
    __syncthreads();
    if (threadIdx.x == 0) {
        float s = 0.f;
        #pragma unroll
        for (int i = 0; i < 8; i++) s += red[i];
        g_t[bj] = s + bias[0];
    }
}

// ---------------------------------------------------------------------------
// K1: S = contex @ Q'^T + t via raw-fp32 tf32 mma.
// A (contex): 3-stage cp.async pipeline. B (Q' = wi*q+wc): register-staged
// 2-buffer path with the fma fused into the fill (g_Qp eliminated).
// Block 128(i) x 64(j), 256 thr = 8 warps (16x64), K=256. grid=(4, B)
// Outputs: S1 (row softmax), rs (row expsums), col expsum partials.
// ---------------------------------------------------------------------------
__global__ void __launch_bounds__(256, 2) k1_score(const float* __restrict__ contex,
                                                   const float* __restrict__ question,
                                                   const float* __restrict__ W) {
    const int b  = blockIdx.y;
    const int i0 = blockIdx.x * 128;
    const int tid = threadIdx.x;
    const int warp = tid >> 5, lane = tid & 31;
    const int g = lane >> 2, t = lane & 3;
    const int wm = warp * 16;

    extern __shared__ float sm[];
    float* As   = sm;                 // 3 x 128 x 36 = 13824
    float* Bs   = sm + 13824;         // 2 x 64 x 36  = 4608
    float* ts   = sm + 18432;         // 64
    float* scol = sm + 18496;         // 8 x 64 = 512
    if (tid < 64) ts[tid] = g_t[b * LQQ + tid];

    const float* Cb = contex   + (size_t)b * LCC * DD;
    const float* Qb = question + (size_t)b * LQQ * DD;

    const int alr = tid >> 1, ako = (tid & 1) * 16;   // A: 4x16B per stage
    const int bjr = tid >> 2, bko = (tid & 3) * 8;    // B: 8 floats per thread
    const unsigned smu = sm2u(sm);

    auto cpA = [&](int s) {
        const float* ga = &Cb[(size_t)(i0 + alr) * DD + s * 32 + ako];
        unsigned da = smu + (unsigned)(((s % 3) * 128 + alr) * 36 + ako) * 4u;
        CPA16(da,      ga);     CPA16(da + 16, ga + 4);
        CPA16(da + 32, ga + 8); CPA16(da + 48, ga + 12);
        CPCOMMIT();
    };

    float4 rq0, rq1;
    auto ldB = [&](int s) {
        const float* qs = &Qb[(size_t)bjr * DD + s * 32 + bko];
        rq0 = *(const float4*)&qs[0];
        rq1 = *(const float4*)&qs[4];
    };
    auto stB = [&](int s) {
        const int kk = s * 32;
        float4 wc0 = *(const float4*)&W[256 + kk + bko];
        float4 wc1 = *(const float4*)&W[256 + kk + bko + 4];
        float4 wi0 = *(const float4*)&W[512 + kk + bko];
        float4 wi1 = *(const float4*)&W[512 + kk + bko + 4];
        float* db = &Bs[(size_t)((s & 1) * 64 + bjr) * 36 + bko];
        db[0] = fmaf(wi0.x, rq0.x, wc0.x); db[1] = fmaf(wi0.y, rq0.y, wc0.y);
        db[2] = fmaf(wi0.z, rq0.z, wc0.z); db[3] = fmaf(wi0.w, rq0.w, wc0.w);
        db[4] = fmaf(wi1.x, rq1.x, wc1.x); db[5] = fmaf(wi1.y, rq1.y, wc1.y);
        db[6] = fmaf(wi1.z, rq1.z, wc1.z); db[7] = fmaf(wi1.w, rq1.w, wc1.w);
    };

    float acc[8][4];
    #pragma unroll
    for (int nt = 0; nt < 8; nt++)
        #pragma unroll
        for (int r = 0; r < 4; r++) acc[nt][r] = 0.f;

    cpA(0); cpA(1);
    ldB(0); stB(0);

    #pragma unroll
    for (int it = 0; it < 8; it++) {
        if (it < 7) { CPWAIT1(); } else { CPWAIT0(); }
        __syncthreads();
        if (it + 2 < 8) cpA(it + 2);
        if (it < 7) ldB(it + 1);
        const float* Ab = As + (size_t)(it % 3) * 128 * 36;
        const float* Bb = Bs + (size_t)(it & 1) * 64 * 36;
        #pragma unroll
        for (int kc = 0; kc < 32; kc += 8) {
            unsigned a0 = *(const unsigned*)&Ab[(size_t)(wm + g) * 36 + kc + t];
            unsigned a1 = *(const unsigned*)&Ab[(size_t)(wm + 8 + g) * 36 + kc + t];
            unsigned a2 = *(const unsigned*)&Ab[(size_t)(wm + g) * 36 + kc + t + 4];
            unsigned a3 = *(const unsigned*)&Ab[(size_t)(wm + 8 + g) * 36 + kc + t + 4];
            #pragma unroll
            for (int nt = 0; nt < 8; nt++) {
                unsigned b0 = *(const unsigned*)&Bb[(size_t)(nt * 8 + g) * 36 + kc + t];
                unsigned b1 = *(const unsigned*)&Bb[(size_t)(nt * 8 + g) * 36 + kc + t + 4];
                mma8(acc[nt][0], acc[nt][1], acc[nt][2], acc[nt][3],
                     a0, a1, a2, a3, b0, b1);
            }
        }
        if (it < 7) stB(it + 1);
        __syncthreads();
    }

    // ---- epilogue: +t[j], col expsums, row softmax -> S1, row sums -> rs ----
    float* S1b = g_S1 + (size_t)b * LCC * LQQ;
    float cs[16];
    #pragma unroll
    for (int c = 0; c < 16; c++) cs[c] = 0.f;

    #pragma unroll
    for (int h = 0; h < 2; h++) {
        const int i = i0 + wm + h * 8 + g;
        float s[16];
        #pragma unroll
        for (int nt = 0; nt < 8; nt++) {
            s[2 * nt]     = acc[nt][2 * h]     + ts[nt * 8 + 2 * t];
            s[2 * nt + 1] = acc[nt][2 * h + 1] + ts[nt * 8 + 2 * t + 1];
        }
        #pragma unroll
        for (int c = 0; c < 16; c++) cs[c] += __expf(s[c]);
        float m = s[0];
        #pragma unroll
        for (int c = 1; c < 16; c++) m = fmaxf(m, s[c]);
        m = fmaxf(m, __shfl_xor_sync(0xffffffffu, m, 1));
        m = fmaxf(m, __shfl_xor_sync(0xffffffffu, m, 2));
        float e[16], sum = 0.f;
        #pragma unroll
        for (int c = 0; c < 16; c++) { e[c] = __expf(s[c] - m); sum += e[c]; }
        sum += __shfl_xor_sync(0xffffffffu, sum, 1);
        sum += __shfl_xor_sync(0xffffffffu, sum, 2);
        const float inv = 1.f / sum;
        #pragma unroll
        for (int nt = 0; nt < 8; nt++) {
            float2 o = make_float2(e[2 * nt] * inv, e[2 * nt + 1] * inv);
            *(float2*)&S1b[(size_t)i * LQQ + nt * 8 + 2 * t] = o;
        }
        if (t == 0) g_rs[b * LCC + i] = sum * __expf(m);
    }
    #pragma unroll
    for (int c = 0; c < 16; c++) {
        cs[c] += __shfl_xor_sync(0xffffffffu, cs[c], 4);
        cs[c] += __shfl_xor_sync(0xffffffffu, cs[c], 8);
        cs[c] += __shfl_xor_sync(0xffffffffu, cs[c], 16);
    }
    if (g == 0) {
        #pragma unroll
        for (int c = 0; c < 16; c++) {
            const int j = (c >> 1) * 8 + 2 * t + (c & 1);
            scol[warp * 64 + j] = cs[c];
        }
    }
    __syncthreads();
    if (tid < 64) {
        float p = 0.f;
        #pragma unroll
        for (int w = 0; w < 8; w++) p += scol[w * 64 + tid];
        g_cpart[blockIdx.x * (BB * LQQ) + b * LQQ + tid] = p;
    }
}

// ---------------------------------------------------------------------------
// K3: C2 = S2^T @ contex, full K=512.  S2[i,j] = S1[i,j]*rs_i*inv_j built on
// the A-fill from L2-hot S1 (no exp).  inv combine folded into prologue.
// Block 64(j) x 64(n), 512 thr = 16 warps 4(m)x4(n), warp tile 16x16.
// A stored [k][j] so the transpose-fill is one float4 STS. grid=(4, B)
// ---------------------------------------------------------------------------
__global__ void __launch_bounds__(512, 2) k3_c2(const float* __restrict__ contex) {
    const int b   = blockIdx.y;
    const int n0  = blockIdx.x * 64;
    const int tid = threadIdx.x;
    const int warp = tid >> 5, lane = tid & 31;
    const int g = lane >> 2, t = lane & 3;
    const int wm = (warp & 3) * 16;
    const int wn = (warp >> 2) * 16;

    extern __shared__ float sm3[];
    float* As   = sm3;                     // 2 x 32 x 68 [k=i][j]
    float* Bs   = sm3 + 4352;              // 3 x 32 x 72 [k][n]
    float* rssm = sm3 + 4352 + 6912;       // 512
    float* sinv = rssm + 512;              // 64

    const float* S1b = g_S1 + (size_t)b * LCC * LQQ;
    const float* Cb  = contex + (size_t)b * LCC * DD;

    rssm[tid] = g_rs[b * LCC + tid];
    if (tid < 64) {
        const int idx = b * LQQ + tid;
        float s = g_cpart[idx] + g_cpart[BB * LQQ + idx]
                + g_cpart[2 * BB * LQQ + idx] + g_cpart[3 * BB * LQQ + idx];
        sinv[tid] = 1.f / s;
    }
    __syncthreads();

    const int iloc = tid >> 4, jo = (tid & 15) * 4;   // A fill: 32 rows x 64 j
    const float4 inv4 = *(const float4*)&sinv[jo];
    const unsigned smu = sm2u(sm3);

    auto cpB = [&](int s) {
        const int buf = s % 3;
        const float* c = &Cb[(size_t)(s * 32 + iloc) * DD + n0 + jo];
        unsigned db = smu + (unsigned)(4352 + (buf * 32 + iloc) * 72 + jo) * 4u;
        CPA16(db, c);
        CPCOMMIT();
    };

    float4 ra; float rsv;
    auto ldA = [&](int s) {
        ra  = *(const float4*)&S1b[(size_t)(s * 32 + iloc) * LQQ + jo];
        rsv = rssm[s * 32 + iloc];
    };
    auto stA = [&](int s) {
        float4 v = make_float4(ra.x * rsv * inv4.x, ra.y * rsv * inv4.y,
                               ra.z * rsv * inv4.z, ra.w * rsv * inv4.w);
        *(float4*)&As[(size_t)((s & 1) * 32 + iloc) * 68 + jo] = v;
    };

    float acc[2][4];
    #pragma unroll
    for (int nt = 0; nt < 2; nt++)
        #pragma unroll
        for (int r = 0; r < 4; r++) acc[nt][r] = 0.f;

    cpB(0); cpB(1);
    ldA(0); stA(0);

    #pragma unroll 4
    for (int it = 0; it < 16; it++) {
        if (it < 15) { CPWAIT1(); } else { CPWAIT0(); }
        __syncthreads();
        if (it + 2 < 16) cpB(it + 2);
        if (it < 15) ldA(it + 1);

        const float* Ab = As + (size_t)(it & 1) * 32 * 68;
        const float* Bb = Bs + (size_t)(it % 3) * 32 * 72;
        #pragma unroll
        for (int kc = 0; kc < 32; kc += 8) {
            unsigned a0 = *(const unsigned*)&Ab[(size_t)(kc + t) * 68 + wm + g];
            unsigned a1 = *(const unsigned*)&Ab[(size_t)(kc + t) * 68 + wm + 8 + g];
            unsigned a2 = *(const unsigned*)&Ab[(size_t)(kc + t + 4) * 68 + wm + g];
            unsigned a3 = *(const unsigned*)&Ab[(size_t)(kc + t + 4) * 68 + wm + 8 + g];
            #pragma unroll
            for (int nt = 0; nt < 2; nt++) {
                const int n = wn + nt * 8 + g;
                unsigned b0 = *(const unsigned*)&Bb[(size_t)(kc + t) * 72 + n];
                unsigned b1 = *(const unsigned*)&Bb[(size_t)(kc + t + 4) * 72 + n];
                mma8(acc[nt][0], acc[nt][1], acc[nt][2], acc[nt][3],
                     a0, a1, a2, a3, b0, b1);
            }
        }
        if (it < 15) stA(it + 1);
        __syncthreads();
    }

    float* outp = g_C2 + (size_t)b * LQQ * DD;
    #pragma unroll
    for (int h = 0; h < 2; h++) {
        const int j = wm + h * 8 + g;
        #pragma unroll
        for (int nt = 0; nt < 2; nt++) {
            float2 o = make_float2(acc[nt][2 * h], acc[nt][2 * h + 1]);
            *(float2*)&outp[(size_t)j * DD + n0 + wn + nt * 8 + 2 * t] = o;
        }
    }
}

// ---------------------------------------------------------------------------
// K4 (R12 version — best measured): one (i-block, chunk) per CTA.
// A = S1 @ question, Bm = S1 @ C2 (K=64); fused output
// [contex | A | contex*A | contex*Bm], smem-staged fragments,
// st.global.cs streaming stores, contex via L2-hot LDG in epilogue.
// grid=(8, B, 4)
// ---------------------------------------------------------------------------
__global__ void __launch_bounds__(256) k4_out(const float* __restrict__ contex,
                                              const float* __restrict__ question,
                                              float* __restrict__ out) {
    const int b   = blockIdx.y;
    const int i0  = blockIdx.x * 64;
    const int c0  = blockIdx.z * 64;
    const int tid = threadIdx.x;
    const int warp = tid >> 5, lane = tid & 31;
    const int g = lane >> 2, t = lane & 3;
    const int wm = (warp & 3) * 16;
    const int wn = (warp >> 2) * 32;

    extern __shared__ float sm4[];
    float* As = sm4;                        // 64 x 68 [i][j]
    float* Bq = sm4 + 64 * 68;              // 64 x 72 [j][n]  (question chunk)
    float* Bc = Bq + 64 * 72;               // 64 x 72 [j][n]  (C2 chunk)

    const float* S1b = g_S1 + (size_t)b * LCC * LQQ;
    const float* Cb  = contex   + (size_t)b * LCC * DD;
    const float* Qb  = question + (size_t)b * LQQ * DD;
    const float* P   = g_C2     + (size_t)b * LQQ * DD;
    float* outb = out + (size_t)b * LCC * 1024;

    const unsigned smu = sm2u(sm4);
    {   // one cp.async group: A tile + both B tiles
        const int lr = tid >> 2, o16 = (tid & 3) * 16;
        const float* sa = &S1b[(size_t)(i0 + lr) * LQQ + o16];
        unsigned da = smu + (unsigned)(lr * 68 + o16) * 4u;
        CPA16(da, sa); CPA16(da + 16, sa + 4); CPA16(da + 32, sa + 8); CPA16(da + 48, sa + 12);
        const float* q = &Qb[(size_t)lr * DD + c0 + o16];
        unsigned dq = smu + (unsigned)(64 * 68 + lr * 72 + o16) * 4u;
        CPA16(dq, q); CPA16(dq + 16, q + 4); CPA16(dq + 32, q + 8); CPA16(dq + 48, q + 12);
        const float* p = &P[(size_t)lr * DD + c0 + o16];
        unsigned dc = smu + (unsigned)(64 * 68 + 64 * 72 + lr * 72 + o16) * 4u;
        CPA16(dc, p); CPA16(dc + 16, p + 4); CPA16(dc + 32, p + 8); CPA16(dc + 48, p + 12);
        CPCOMMIT();
    }
    CPWAIT0();
    __syncthreads();

    float accq[4][4], accc[4][4];
    #pragma unroll
    for (int nt = 0; nt < 4; nt++)
        #pragma unroll
        for (int r = 0; r < 4; r++) { accq[nt][r] = 0.f; accc[nt][r] = 0.f; }

    #pragma unroll
    for (int kc = 0; kc < 64; kc += 8) {
        unsigned a0 = *(const unsigned*)&As[(size_t)(wm + g) * 68 + kc + t];
        unsigned a1 = *(const unsigned*)&As[(size_t)(wm + 8 + g) * 68 + kc + t];
        unsigned a2 = *(const unsigned*)&As[(size_t)(wm + g) * 68 + kc + t + 4];
        unsigned a3 = *(const unsigned*)&As[(size_t)(wm + 8 + g) * 68 + kc + t + 4];
        #pragma unroll
        for (int nt = 0; nt < 4; nt++) {
            const int n = wn + nt * 8 + g;
            unsigned q0 = *(const unsigned*)&Bq[(size_t)(kc + t) * 72 + n];
            unsigned q1 = *(const unsigned*)&Bq[(size_t)(kc + t + 4) * 72 + n];
            mma8(accq[nt][0], accq[nt][1], accq[nt][2], accq[nt][3],
                 a0, a1, a2, a3, q0, q1);
            unsigned c0r = *(const unsigned*)&Bc[(size_t)(kc + t) * 72 + n];
            unsigned c1r = *(const unsigned*)&Bc[(size_t)(kc + t + 4) * 72 + n];
            mma8(accc[nt][0], accc[nt][1], accc[nt][2], accc[nt][3],
                 a0, a1, a2, a3, c0r, c1r);
        }
    }
    __syncthreads();   // B tiles consumed -> reuse as fragment stage

    // stage fragments: Bq region holds A-frags, Bc region holds Bm-frags
    #pragma unroll
    for (int h = 0; h < 2; h++) {
        const int r = wm + h * 8 + g;
        #pragma unroll
        for (int nt = 0; nt < 4; nt++) {
            const int c = wn + nt * 8 + 2 * t;
            *(float2*)&Bq[(size_t)r * 72 + c] =
                make_float2(accq[nt][2 * h], accq[nt][2 * h + 1]);
            *(float2*)&Bc[(size_t)r * 72 + c] =
                make_float2(accc[nt][2 * h], accc[nt][2 * h + 1]);
        }
    }
    __syncthreads();

    // coalesced output: 4 passes x (LDG.128 contex + 4x STG.128.cs)
    const int orw = tid >> 4;              // 0..15
    const int occ4 = (tid & 15) * 4;       // 0..60
    #pragma unroll
    for (int p = 0; p < 4; p++) {
        const int r = p * 16 + orw;
        float4 a4 = *(const float4*)&Bq[(size_t)r * 72 + occ4];
        float4 m4 = *(const float4*)&Bc[(size_t)r * 72 + occ4];
        float4 cv = *(const float4*)&Cb[(size_t)(i0 + r) * DD + c0 + occ4];
        float4 pa = make_float4(cv.x * a4.x, cv.y * a4.y, cv.z * a4.z, cv.w * a4.w);
        float4 pb = make_float4(cv.x * m4.x, cv.y * m4.y, cv.z * m4.z, cv.w * m4.w);
        float* orow = &outb[(size_t)(i0 + r) * 1024 + c0 + occ4];
        stg_cs(orow,       cv);   // contex
        stg_cs(orow + 256, a4);   // A
        stg_cs(orow + 512, pa);   // contex * A
        stg_cs(orow + 768, pb);   // contex * Bm
    }
}

// ---------------------------------------------------------------------------
extern "C" void kernel_launch(void* const* d_in, const int* in_sizes, int n_in,
                              void* d_out, int out_size) {
    const float* contex   = (const float*)d_in[0];
    const float* question = (const float*)d_in[1];
    const float* W        = (const float*)d_in[2];
    const float* bias     = (const float*)d_in[3];
    float* out = (float*)d_out;

    const int k1smem = 19008 * (int)sizeof(float);                          // 76032
    const int k3smem = (4352 + 6912 + 512 + 64) * (int)sizeof(float);       // 47360
    const int k4smem = (64 * 68 + 2 * 64 * 72) * (int)sizeof(float);        // 54272
    cudaFuncSetAttribute(k1_score, cudaFuncAttributeMaxDynamicSharedMemorySize, k1smem);
    cudaFuncSetAttribute(k3_c2,    cudaFuncAttributeMaxDynamicSharedMemorySize, k3smem);
    cudaFuncSetAttribute(k4_out,   cudaFuncAttributeMaxDynamicSharedMemorySize, k4smem);

    k0_t<<<BB * LQQ, 256>>>(question, W, bias);
    k1_score<<<dim3(4, BB), 256, k1smem>>>(contex, question, W);
    k3_c2<<<dim3(4, BB), 512, k3smem>>>(contex);
    k4_out<<<dim3(8, BB, 4), 256, k4smem>>>(contex, question, out);
}